// round 13
// baseline (speedup 1.0000x reference)
#include <cuda_runtime.h>
#include <cuda_bf16.h>

// ROI bilinear pooling (tf.image.resize half-pixel-center semantics, per ROI).
// img:  (1, 64, 64, 1024) float32, NHWC
// rois: (1, R, 4) int32  [x, y, w, h]
// out:  (1, R, 7, 7, 1024) float32
//
// R11: CTA per output row (r, py) — the winning R3 shape — plus branch-free
// column dedup: bilinear columns shared between adjacent px are loaded once.
// Loads are PREDICATED (no BSSY branches, no wavefronts when off, still
// independently batchable); reuse resolved by CTA-uniform SEL chains.

#define POOL 7
#define HW   64
#define C    1024
#define C4   (C / 4)

// Predicated 16B load: when pred==0, no memory transaction is issued and the
// destination registers are left undefined (consumed only behind selects).
__device__ __forceinline__ float4 ldg4_if(const float4* p, int pred)
{
    float4 v;
    asm("{\n\t"
        ".reg .pred q;\n\t"
        "setp.ne.s32 q, %5, 0;\n\t"
        "@q ld.global.nc.v4.f32 {%0,%1,%2,%3}, [%4];\n\t"
        "}"
        : "=f"(v.x), "=f"(v.y), "=f"(v.z), "=f"(v.w)
        : "l"(p), "r"(pred));
    return v;
}

__device__ __forceinline__ float4 sel4(int c, float4 a, float4 b)
{
    float4 r;
    r.x = c ? a.x : b.x;
    r.y = c ? a.y : b.y;
    r.z = c ? a.z : b.z;
    r.w = c ? a.w : b.w;
    return r;
}

__global__ __launch_bounds__(256) void roi_pool_row_kernel(
    const float* __restrict__ img,
    const int*   __restrict__ rois,
    float*       __restrict__ out)
{
    const int row = blockIdx.x;          // r*7 + py
    const int r   = row / POOL;
    const int py  = row - r * POOL;

    // ROI box [x, y, w, h] (broadcast load)
    const int4 roi = __ldg(((const int4*)rois) + r);
    const int bx = roi.x, by = roi.y, bw = roi.z, bh = roi.w;

    // ---- vertical coords: once per CTA ----
    const float sy = (py + 0.5f) * ((float)bh / (float)POOL) - 0.5f;
    const float fy = floorf(sy);
    const float ty = sy - fy;
    const int   iy = (int)fy;
    const int   y0 = by + min(max(iy,     0), bh - 1);
    const int   y1 = by + min(max(iy + 1, 0), bh - 1);
    const float wty0 = 1.0f - ty;

    const int c = threadIdx.x;           // channel slice 0..255
    const float4* r0 = ((const float4*)img) + (size_t)y0 * (HW * C4) + c;
    const float4* r1 = ((const float4*)img) + (size_t)y1 * (HW * C4) + c;
    float4* outp = ((float4*)out) + (size_t)row * (POOL * C4) + c;

    // ---- horizontal coord tables (fully unrolled -> registers) ----
    const float xscale = (float)bw / (float)POOL;
    const int   xmax   = bw - 1;
    int   x0t[POOL], x1t[POOL];
    float txt[POOL];
#pragma unroll
    for (int px = 0; px < POOL; px++) {
        const float sx = (px + 0.5f) * xscale - 0.5f;
        const float fx = floorf(sx);
        txt[px] = sx - fx;
        const int ix = (int)fx;
        x0t[px] = bx + min(max(ix,     0), xmax);
        x1t[px] = bx + min(max(ix + 1, 0), xmax);
    }

    float4 v0p, v1p;                     // previous pixel's blended columns

#pragma unroll
    for (int px = 0; px < POOL; px++) {
        const int xo0 = x0t[px] * C4;
        const int xo1 = x1t[px] * C4;

        // ---- column v0 = vertical blend at x0 (reuse from previous px) ----
        const int same00 = (px > 0) && (x0t[px] == x0t[px - 1]);
        const int same01 = (px > 0) && (x0t[px] == x1t[px - 1]);
        const int need0  = !(same00 | same01);

        const float4 a = ldg4_if(r0 + xo0, need0);
        const float4 g = ldg4_if(r1 + xo0, need0);
        float4 l0;
        l0.x = a.x * wty0 + g.x * ty;
        l0.y = a.y * wty0 + g.y * ty;
        l0.z = a.z * wty0 + g.z * ty;
        l0.w = a.w * wty0 + g.w * ty;

        float4 v0 = l0;
        if (px > 0) v0 = sel4(same00, v0p, sel4(same01, v1p, l0));

        // ---- column v1 = vertical blend at x1 ----
        const int same10 = (x1t[px] == x0t[px]);               // clamp dup
        const int same11 = (px > 0) && (x1t[px] == x1t[px - 1]);
        const int need1  = !(same10 | same11);

        const float4 b = ldg4_if(r0 + xo1, need1);
        const float4 d = ldg4_if(r1 + xo1, need1);
        float4 l1;
        l1.x = b.x * wty0 + d.x * ty;
        l1.y = b.y * wty0 + d.y * ty;
        l1.z = b.z * wty0 + d.z * ty;
        l1.w = b.w * wty0 + d.w * ty;

        float4 v1;
        if (px > 0) v1 = sel4(same10, v0, sel4(same11, v1p, l1));
        else        v1 = sel4(same10, v0, l1);

        // ---- horizontal blend + store ----
        const float tx   = txt[px];
        const float wtx0 = 1.0f - tx;
        float4 o;
        o.x = v0.x * wtx0 + v1.x * tx;
        o.y = v0.y * wtx0 + v1.y * tx;
        o.z = v0.z * wtx0 + v1.z * tx;
        o.w = v0.w * wtx0 + v1.w * tx;

        outp[px * C4] = o;

        v0p = v0;
        v1p = v1;
    }
}

extern "C" void kernel_launch(void* const* d_in, const int* in_sizes, int n_in,
                              void* d_out, int out_size)
{
    const float* img  = (const float*)d_in[0];
    const int*   rois = (const int*)d_in[1];
    float*       out  = (float*)d_out;

    const int R = in_sizes[1] / 4;       // number of ROIs
    const int blocks = R * POOL;         // one CTA per output row

    roi_pool_row_kernel<<<blocks, 256>>>(img, rois, out);
}

// round 14
// speedup vs baseline: 1.3041x; 1.3041x over previous
#include <cuda_runtime.h>
#include <cuda_bf16.h>

// ROI bilinear pooling (tf.image.resize half-pixel-center semantics, per ROI).
// img:  (1, 64, 64, 1024) float32, NHWC
// rois: (1, R, 4) int32  [x, y, w, h]
// out:  (1, R, 7, 7, 1024) float32
//
// R13: CTA per output row (R3 shape) + column dedup, register-frugal:
// rolled px loop (no unroll -> short live ranges), no coordinate tables,
// predicated loads (no BSSY, no wavefront when off), CTA-uniform selects.

#define POOL 7
#define HW   64
#define C    1024
#define C4   (C / 4)

// Predicated 16B load: when pred==0 no transaction is issued; dest regs are
// undefined but only ever consumed behind selects that discard them.
__device__ __forceinline__ float4 ldg4_if(const float4* p, int pred)
{
    float4 v;
    asm("{\n\t"
        ".reg .pred q;\n\t"
        "setp.ne.s32 q, %5, 0;\n\t"
        "@q ld.global.nc.v4.f32 {%0,%1,%2,%3}, [%4];\n\t"
        "}"
        : "=f"(v.x), "=f"(v.y), "=f"(v.z), "=f"(v.w)
        : "l"(p), "r"(pred));
    return v;
}

__device__ __forceinline__ float4 sel4(int c, float4 a, float4 b)
{
    float4 r;
    r.x = c ? a.x : b.x;
    r.y = c ? a.y : b.y;
    r.z = c ? a.z : b.z;
    r.w = c ? a.w : b.w;
    return r;
}

__global__ __launch_bounds__(256) void roi_pool_row_kernel(
    const float* __restrict__ img,
    const int*   __restrict__ rois,
    float*       __restrict__ out)
{
    const int row = blockIdx.x;          // r*7 + py
    const int r   = row / POOL;
    const int py  = row - r * POOL;

    // ROI box [x, y, w, h] (broadcast load)
    const int4 roi = __ldg(((const int4*)rois) + r);
    const int bx = roi.x, by = roi.y, bw = roi.z, bh = roi.w;

    // ---- vertical coords: once per CTA ----
    const float sy = (py + 0.5f) * ((float)bh / (float)POOL) - 0.5f;
    const float fy = floorf(sy);
    const float ty = sy - fy;
    const int   iy = (int)fy;
    const int   y0 = by + min(max(iy,     0), bh - 1);
    const int   y1 = by + min(max(iy + 1, 0), bh - 1);
    const float wty0 = 1.0f - ty;

    const int c = threadIdx.x;           // channel slice 0..255
    const float4* r0 = ((const float4*)img) + (size_t)y0 * (HW * C4) + c;
    const float4* r1 = ((const float4*)img) + (size_t)y1 * (HW * C4) + c;
    float4* outp = ((float4*)out) + (size_t)row * (POOL * C4) + c;

    const float xscale = (float)bw / (float)POOL;
    const int   xmax   = bw - 1;

    // Carried state: previous pixel's columns and their blended values.
    int    px0 = -1, px1 = -1;
    float4 v0p = make_float4(0.f, 0.f, 0.f, 0.f);
    float4 v1p = v0p;

#pragma unroll 1
    for (int px = 0; px < POOL; px++) {
        // ---- horizontal coords (CTA-uniform, recomputed inline) ----
        const float sx = (px + 0.5f) * xscale - 0.5f;
        const float fx = floorf(sx);
        const float tx = sx - fx;
        const int   ix = (int)fx;
        const int   x0 = bx + min(max(ix,     0), xmax);
        const int   x1 = bx + min(max(ix + 1, 0), xmax);

        // ---- column v0 = vertical blend at x0 (reuse if seen last px) ----
        const int s00 = (x0 == px0);
        const int s01 = (x0 == px1);
        const int need0 = !(s00 | s01);

        const float4 a = ldg4_if(r0 + x0 * C4, need0);
        const float4 g = ldg4_if(r1 + x0 * C4, need0);
        float4 l0;
        l0.x = a.x * wty0 + g.x * ty;
        l0.y = a.y * wty0 + g.y * ty;
        l0.z = a.z * wty0 + g.z * ty;
        l0.w = a.w * wty0 + g.w * ty;
        const float4 v0 = sel4(s00, v0p, sel4(s01, v1p, l0));

        // ---- column v1 = vertical blend at x1 ----
        const int s10 = (x1 == x0);      // clamp duplicate
        const int s11 = (x1 == px1);
        const int need1 = !(s10 | s11);

        const float4 b = ldg4_if(r0 + x1 * C4, need1);
        const float4 d = ldg4_if(r1 + x1 * C4, need1);
        float4 l1;
        l1.x = b.x * wty0 + d.x * ty;
        l1.y = b.y * wty0 + d.y * ty;
        l1.z = b.z * wty0 + d.z * ty;
        l1.w = b.w * wty0 + d.w * ty;
        const float4 v1 = sel4(s10, v0, sel4(s11, v1p, l1));

        // ---- horizontal blend + store ----
        const float wtx0 = 1.0f - tx;
        float4 o;
        o.x = v0.x * wtx0 + v1.x * tx;
        o.y = v0.y * wtx0 + v1.y * tx;
        o.z = v0.z * wtx0 + v1.z * tx;
        o.w = v0.w * wtx0 + v1.w * tx;

        outp[px * C4] = o;

        px0 = x0; px1 = x1;
        v0p = v0; v1p = v1;
    }
}

extern "C" void kernel_launch(void* const* d_in, const int* in_sizes, int n_in,
                              void* d_out, int out_size)
{
    const float* img  = (const float*)d_in[0];
    const int*   rois = (const int*)d_in[1];
    float*       out  = (float*)d_out;

    const int R = in_sizes[1] / 4;       // number of ROIs
    const int blocks = R * POOL;         // one CTA per output row

    roi_pool_row_kernel<<<blocks, 256>>>(img, rois, out);
}